// round 7
// baseline (speedup 1.0000x reference)
#include <cuda_runtime.h>
#include <cuda_fp16.h>
#include <mma.h>
#include <cuda_pipeline.h>
#include <cstdint>

using namespace nvcuda;

// Problem dims
#define M_TOT 8192          // 4*2048
#define N_TOT 14336
#define K_TOT 4096
#define NPACK (N_TOT * (K_TOT / 2))

// GEMM tiling (fp16 wmma 16x16x16, single K pass)
#define BM 128
#define BN 128
#define BK 64               // 64 fp16 per stage row (128B)
#define LDT 72              // smem row stride (halves): 64 + 8 pad (16B-aligned rows)
#define NT (K_TOT / BK)     // 64 k-iterations
#define STAGES 3
#define STAGE_HALVES ((BM + BN) * LDT)              // 18432 halves = 36864 B
#define SMEM_BYTES (STAGES * STAGE_HALVES * 2)      // 110592 B dynamic

// Rasterization: supertiles of GROUP_M m-tiles (fast) x all n-tiles
#define TILES_M (M_TOT / BM)      // 64
#define TILES_N (N_TOT / BN)      // 112
#define GROUP_M 16

// Scratch (static device globals: allocation-free per harness rules)
__device__ __align__(256) __half g_Ah[(size_t)M_TOT * K_TOT];   // 67 MB: x in fp16
__device__ __align__(256) __half g_Qh[(size_t)N_TOT * K_TOT];   // 117 MB: weights fp16
__device__ int g_swap_sb;   // 1 => sb0 is actually bias
__device__ int g_qw_i32;    // 1 => qweight stored as int32 (harness promoted int8)

// ---------------------------------------------------------------------------
// Probes: scale strictly positive (abs-max/7) vs bias (has negatives);
// qweight dtype: int32-promoted iff first 4096 words all in [-128,127].
// ---------------------------------------------------------------------------
__global__ void probe_kernel(const float* __restrict__ sb0,
                             const void* __restrict__ qw_raw) {
    __shared__ int s_neg, s_small;
    if (threadIdx.x == 0) { s_neg = 0; s_small = 1; }
    __syncthreads();
    int local_neg = 0;
    for (int i = threadIdx.x; i < N_TOT; i += blockDim.x)
        if (sb0[i] < 0.0f) local_neg = 1;
    if (local_neg) atomicOr(&s_neg, 1);
    const int* qw32 = (const int*)qw_raw;
    int local_big = 0;
    for (int i = threadIdx.x; i < 4096; i += blockDim.x) {
        int v = qw32[i];
        if (v < -128 || v > 127) local_big = 1;
    }
    if (local_big) atomicAnd(&s_small, 0);
    __syncthreads();
    if (threadIdx.x == 0) { g_swap_sb = s_neg; g_qw_i32 = s_small; }
}

// ---------------------------------------------------------------------------
// Prep 1: x fp32 -> fp16 (round-to-nearest).
// ---------------------------------------------------------------------------
__global__ void conv_x_kernel(const float* __restrict__ x) {
    int idx = blockIdx.x * blockDim.x + threadIdx.x;
    if (idx >= M_TOT * K_TOT) return;
    g_Ah[idx] = __float2half_rn(x[idx]);
}

// ---------------------------------------------------------------------------
// Prep 2: unpack 4-bit pairs -> fp16 integers in [-8,7] (exact in fp16).
// Packed byte j of row n: high nibble = q[n][2j], low = q[n][2j+1].
// ---------------------------------------------------------------------------
__global__ void unpack_w_kernel(const void* __restrict__ qw_raw) {
    int idx = blockIdx.x * blockDim.x + threadIdx.x;
    if (idx >= NPACK) return;
    int v;
    if (g_qw_i32) v = ((const int*)qw_raw)[idx];
    else          v = (int)((const signed char*)qw_raw)[idx];
    int n = idx / (K_TOT / 2);
    int j = idx - n * (K_TOT / 2);
    int hi = v >> 4;
    int lo = ((v & 15) ^ 8) - 8;
    g_Qh[(size_t)n * K_TOT + 2 * j]     = __float2half_rn((float)hi);
    g_Qh[(size_t)n * K_TOT + 2 * j + 1] = __float2half_rn((float)lo);
}

// ---------------------------------------------------------------------------
// GEMM: out[m,n] = scale[n] * sum_k Ah[m,k]*Qh[n,k] + bias[n]
// 128x128 tile, BK=64, 3-stage cp.async, ONE __syncthreads per k-iter.
// Supertile rasterization: GROUP_M m-tiles fastest -> A stays L2-resident
// across the n-sweep, B read once per group. 8 warps (2x4), warp tile 64x32.
// ---------------------------------------------------------------------------
__global__ __launch_bounds__(256) void gemm_f16_kernel(const float* __restrict__ sb0,
                                                       const float* __restrict__ sb1,
                                                       float* __restrict__ out) {
    extern __shared__ __align__(16) char dsm[];
    __half* smem_h = reinterpret_cast<__half*>(dsm);

    const int tid = threadIdx.x;

    // Supertile raster: bid -> (mt, nt); mt fastest within a GROUP_M band.
    const int bid = blockIdx.x;
    const int band = bid / (GROUP_M * TILES_N);          // which m-band
    const int within = bid - band * (GROUP_M * TILES_N);
    const int mt = band * GROUP_M + (within % GROUP_M);
    const int nt = within / GROUP_M;
    const int m0 = mt * BM;
    const int n0 = nt * BN;

    auto Abuf = [&](int s) { return smem_h + s * STAGE_HALVES; };
    auto Bbuf = [&](int s) { return smem_h + s * STAGE_HALVES + BM * LDT; };

    // Per stage: A = 128 rows x 8 chunks(16B) = 1024 chunks, B same.
    auto issue = [&](int t) {
        const int s = t % STAGES;
        const int k0 = t * BK;
        __half* Ab = Abuf(s);
        __half* Bb = Bbuf(s);
        #pragma unroll
        for (int c = 0; c < 4; ++c) {
            int g = c * 256 + tid;
            int row = g >> 3, col = (g & 7) * 8;     // halves
            __pipeline_memcpy_async(Ab + row * LDT + col,
                                    g_Ah + (size_t)(m0 + row) * K_TOT + k0 + col, 16);
        }
        #pragma unroll
        for (int c = 0; c < 4; ++c) {
            int g = c * 256 + tid;
            int row = g >> 3, col = (g & 7) * 8;
            __pipeline_memcpy_async(Bb + row * LDT + col,
                                    g_Qh + (size_t)(n0 + row) * K_TOT + k0 + col, 16);
        }
    };

    const int warpId = tid >> 5;
    const int lane   = tid & 31;
    const int wm = (warpId & 1) * 64;   // 2 warps along M
    const int wn = (warpId >> 1) * 32;  // 4 warps along N

    wmma::fragment<wmma::matrix_a, 16, 16, 16, __half, wmma::row_major> fa[4];
    wmma::fragment<wmma::matrix_b, 16, 16, 16, __half, wmma::col_major> fb[2];
    wmma::fragment<wmma::accumulator, 16, 16, 16, float> acc[4][2];
    #pragma unroll
    for (int i = 0; i < 4; ++i)
        #pragma unroll
        for (int j = 0; j < 2; ++j)
            wmma::fill_fragment(acc[i][j], 0.0f);

    issue(0); __pipeline_commit();
    issue(1); __pipeline_commit();

    for (int t = 0; t < NT; ++t) {
        __pipeline_wait_prior((t + 1 < NT) ? 1 : 0);   // group t complete
        __syncthreads();                               // all warps done with t-1; t visible
        if (t + 2 < NT) {                              // refill buffer (t-1)%3 — now safe
            issue(t + 2);
            __pipeline_commit();
        }
        const __half* As = Abuf(t % STAGES);
        const __half* Bs = Bbuf(t % STAGES);
        #pragma unroll
        for (int kk = 0; kk < BK; kk += 16) {
            #pragma unroll
            for (int i = 0; i < 4; ++i)
                wmma::load_matrix_sync(fa[i], As + (wm + i * 16) * LDT + kk, LDT);
            #pragma unroll
            for (int j = 0; j < 2; ++j)
                wmma::load_matrix_sync(fb[j], Bs + (wn + j * 16) * LDT + kk, LDT);
            #pragma unroll
            for (int i = 0; i < 4; ++i)
                #pragma unroll
                for (int j = 0; j < 2; ++j)
                    wmma::mma_sync(acc[i][j], fa[i], fb[j], acc[i][j]);
        }
    }

    // Epilogue: stage 16x16 tiles through per-warp smem, fuse scale/bias.
    __syncthreads();
    const float* scale = g_swap_sb ? sb1 : sb0;
    const float* bias  = g_swap_sb ? sb0 : sb1;
    float* cbuf = reinterpret_cast<float*>(dsm) + warpId * 256;   // 1KB/warp

    #pragma unroll
    for (int i = 0; i < 4; ++i) {
        #pragma unroll
        for (int j = 0; j < 2; ++j) {
            wmma::store_matrix_sync(cbuf, acc[i][j], 16, wmma::mem_row_major);
            __syncwarp();
            const int gm_base = m0 + wm + i * 16;
            const int gn_base = n0 + wn + j * 16;
            #pragma unroll
            for (int e = lane; e < 256; e += 32) {
                int r = e >> 4, c = e & 15;
                int gn = gn_base + c;
                out[(size_t)(gm_base + r) * N_TOT + gn] = cbuf[e] * scale[gn] + bias[gn];
            }
            __syncwarp();
        }
    }
}

// ---------------------------------------------------------------------------
extern "C" void kernel_launch(void* const* d_in, const int* in_sizes, int n_in,
                              void* d_out, int out_size) {
    (void)out_size;
    // Bind by element count: x 33554432 | qweight 29360128 | scale/bias 14336
    int ix = 0, iq = 1, isb0 = 2, isb1 = 3, nsb = 0;
    int sb_idx[2] = {2, 3};
    for (int i = 0; i < n_in && i < 8; ++i) {
        if (in_sizes[i] == M_TOT * K_TOT) ix = i;
        else if (in_sizes[i] == NPACK) iq = i;
        else if (in_sizes[i] == N_TOT && nsb < 2) sb_idx[nsb++] = i;
    }
    if (nsb == 2) { isb0 = sb_idx[0]; isb1 = sb_idx[1]; }

    const float* x   = (const float*)d_in[ix];
    const void*  qw  = d_in[iq];
    const float* sb0 = (const float*)d_in[isb0];
    const float* sb1 = (const float*)d_in[isb1];
    float*       out = (float*)d_out;

    probe_kernel<<<1, 1024>>>(sb0, qw);

    const int totalA = M_TOT * K_TOT;
    conv_x_kernel<<<(totalA + 255) / 256, 256>>>(x);
    unpack_w_kernel<<<(NPACK + 255) / 256, 256>>>(qw);

    cudaFuncSetAttribute(gemm_f16_kernel,
                         cudaFuncAttributeMaxDynamicSharedMemorySize, SMEM_BYTES);
    gemm_f16_kernel<<<TILES_M * TILES_N, 256, SMEM_BYTES>>>(sb0, sb1, out);
}